// round 9
// baseline (speedup 1.0000x reference)
#include <cuda_runtime.h>

// Problem constants (fixed shapes per reference)
#define IN_F     256
#define OUT_F    256
#define BATCH    512
#define NSEG     16
#define NT       49            // (N-1)*SEGMENTS + 1
#define KDIM     (IN_F * NT)   // 12544

// i split into 37 uneven pieces; grid = 4 b-tiles * 2 o-halves * 37 = 296 CTAs
// = exactly 2 CTAs per SM. Splits 0..33 have 7 i's, 34..36 have 6 (34*7+3*6=256).
#define I_SPLIT  37
#define I_MAX    7
#define B_TILE   128
#define B_SUB    16                 // per thread (8 b-lanes * 16 = 128)

// Static device scratch (no allocations allowed)
__device__ float  g_wt[KDIM * OUT_F];                 // transposed weights [k][o], 12.85 MB
__device__ float  g_part[I_SPLIT * BATCH * OUT_F];    // split-K partials, 18.5 MB

// ---------------------------------------------------------------------------
// Kernel 1: DIRECT transpose w[o][k] -> wt[k][o], no shared memory.
// ---------------------------------------------------------------------------
__global__ __launch_bounds__(256) void transpose_w_kernel(const float* __restrict__ w) {
    const int t     = threadIdx.x;
    const int lane  = t & 31;                         // o within tile
    const int wrp   = t >> 5;                         // 0..7
    const int o     = blockIdx.y * 32 + lane;
    const int kbase = blockIdx.x * 128 + wrp * 16;    // 16 consecutive k per thread

    const float* src = w + (size_t)o * KDIM + kbase;
    const float4 v0 = __ldg((const float4*)(src + 0));
    const float4 v1 = __ldg((const float4*)(src + 4));
    const float4 v2 = __ldg((const float4*)(src + 8));
    const float4 v3 = __ldg((const float4*)(src + 12));

    float vv[16] = { v0.x, v0.y, v0.z, v0.w,
                     v1.x, v1.y, v1.z, v1.w,
                     v2.x, v2.y, v2.z, v2.w,
                     v3.x, v3.y, v3.z, v3.w };

    float* dst = g_wt + (size_t)kbase * OUT_F + o;
#pragma unroll
    for (int c = 0; c < 16; c++) {
        dst[(size_t)c * OUT_F] = vv[c];               // 128B coalesced per warp
    }
}

// ---------------------------------------------------------------------------
// Kernel 2 (main): fused basis + gather-contraction.
// Grid: (4 b-tiles, 2 o-halves, 37 i-splits) = 296 CTAs = 2 per SM.
// Block: 256 threads = 32 o-quads x 8 b-lanes; 2 CTAs/SM -> 32 warps/SM.
// Each thread: 16 b x 4 o x (6|7) i.
// Chebyshev-Lobatto n=4 nodes: [-1, -0.5, 0.5, 1].
// ---------------------------------------------------------------------------
__global__ __launch_bounds__(256, 2) void pp_main_kernel(const float* __restrict__ x) {
    __shared__ float4 s_bas[I_MAX][B_TILE];
    __shared__ int    s_off[I_MAX][B_TILE];

    const int tid   = threadIdx.x;
    const int oq    = tid & 31;          // o = oh*128 + oq*4
    const int blane = tid >> 5;          // 0..7 (uniform per warp)
    const int bt0   = blockIdx.x * B_TILE;
    const int oh    = blockIdx.y;        // 0..1
    const int split = blockIdx.z;        // 0..36
    const int icnt  = (split < 34) ? 7 : 6;
    const int i0    = (split < 34) ? split * 7 : 238 + (split - 34) * 6;

    // Stage basis + weight-row byte-offsets: one thread per b-row.
    if (tid < B_TILE) {
        const int bl = tid;
        const float* xrow = x + (size_t)(bt0 + bl) * IN_F + i0;
#pragma unroll
        for (int il = 0; il < I_MAX; il++) {
            if (il >= icnt) break;
            const float xv = xrow[il];

            int s = (int)((xv + 1.0f) * 0.5f * (float)NSEG);
            s = min(max(s, 0), NSEG - 1);
            const float xmin = (float)s * (2.0f / (float)NSEG) - 1.0f;
            const float xi   = (xv - xmin) * (float)NSEG - 1.0f;

            const float d0 = xi + 1.0f;
            const float d1 = xi + 0.5f;
            const float d2 = xi - 0.5f;
            const float d3 = xi - 1.0f;

            float4 b;
            b.x = d1 * d2 * d3 * (-1.0f / 1.5f);
            b.y = d0 * d2 * d3 * ( 1.0f / 0.75f);
            b.z = d0 * d1 * d3 * (-1.0f / 0.75f);
            b.w = d0 * d1 * d2 * ( 1.0f / 1.5f);

            s_bas[il][bl] = b;
            s_off[il][bl] = 3 * s * (OUT_F * 4);   // byte offset
        }
    }
    __syncthreads();

    float4 acc[B_SUB];
#pragma unroll
    for (int bb = 0; bb < B_SUB; bb++) acc[bb] = make_float4(0.f, 0.f, 0.f, 0.f);

    const int bloc0 = blane * B_SUB;
    const int ocol  = oh * 128 + oq * 4;

#pragma unroll 1
    for (int ii = 0; ii < icnt; ii++) {
        const char* wt_i = (const char*)(g_wt + (size_t)(i0 + ii) * (NT * OUT_F) + ocol);

#pragma unroll
        for (int bb = 0; bb < B_SUB; bb++) {
            const float4 bas = s_bas[ii][bloc0 + bb];   // warp-uniform broadcast
            const int    off = s_off[ii][bloc0 + bb];

            const char* p = wt_i + off;
            float4 w0 = __ldg((const float4*)(p + 0 * (OUT_F * 4)));
            float4 w1 = __ldg((const float4*)(p + 1 * (OUT_F * 4)));
            float4 w2 = __ldg((const float4*)(p + 2 * (OUT_F * 4)));
            float4 w3 = __ldg((const float4*)(p + 3 * (OUT_F * 4)));

            acc[bb].x = fmaf(bas.x, w0.x, fmaf(bas.y, w1.x, fmaf(bas.z, w2.x, fmaf(bas.w, w3.x, acc[bb].x))));
            acc[bb].y = fmaf(bas.x, w0.y, fmaf(bas.y, w1.y, fmaf(bas.z, w2.y, fmaf(bas.w, w3.y, acc[bb].y))));
            acc[bb].z = fmaf(bas.x, w0.z, fmaf(bas.y, w1.z, fmaf(bas.z, w2.z, fmaf(bas.w, w3.z, acc[bb].z))));
            acc[bb].w = fmaf(bas.x, w0.w, fmaf(bas.y, w1.w, fmaf(bas.z, w2.w, fmaf(bas.w, w3.w, acc[bb].w))));
        }
    }

    float* outp = g_part + (size_t)split * (BATCH * OUT_F);
#pragma unroll
    for (int bb = 0; bb < B_SUB; bb++) {
        const int b = bt0 + bloc0 + bb;
        *(float4*)(outp + (size_t)b * OUT_F + ocol) = acc[bb];
    }
}

// ---------------------------------------------------------------------------
// Kernel 3: reduce the 37 i-split partials. Block = 512 threads =
// 64 outputs x 8 k-groups (5/5/5/5/5/4/4/4 partials each); fixed-order tree.
// Grid = 512 CTAs.
// ---------------------------------------------------------------------------
__global__ __launch_bounds__(512) void reduce_kernel(float* __restrict__ out) {
    __shared__ float4 sm[512];
    const int tid = threadIdx.x;
    const int o4  = blockIdx.x * 64 + (tid & 63);   // float4 index, 0..32767
    const int kg  = tid >> 6;                        // 0..7

    const int start = (kg < 5) ? kg * 5 : 25 + (kg - 5) * 4;
    const int cnt   = (kg < 5) ? 5 : 4;

    const float4* p = (const float4*)g_part + o4;
    float4 s = make_float4(0.f, 0.f, 0.f, 0.f);
#pragma unroll
    for (int k = 0; k < 5; k++) {
        if (k >= cnt) break;
        float4 v = __ldg(p + (size_t)(start + k) * (BATCH * OUT_F / 4));
        s.x += v.x; s.y += v.y; s.z += v.z; s.w += v.w;
    }
    sm[tid] = s;
    __syncthreads();

    if (kg < 2) {
        float4 a = sm[tid], b = sm[tid + 128], c = sm[tid + 256], d = sm[tid + 384];
        float4 r;
        r.x = ((a.x + b.x) + c.x) + d.x;
        r.y = ((a.y + b.y) + c.y) + d.y;
        r.z = ((a.z + b.z) + c.z) + d.z;
        r.w = ((a.w + b.w) + c.w) + d.w;
        sm[tid] = r;
    }
    __syncthreads();
    if (kg == 0) {
        float4 a = sm[tid], b = sm[tid + 64];
        float4 r;
        r.x = a.x + b.x; r.y = a.y + b.y; r.z = a.z + b.z; r.w = a.w + b.w;
        ((float4*)out)[o4] = r;
    }
}

// ---------------------------------------------------------------------------
extern "C" void kernel_launch(void* const* d_in, const int* in_sizes, int n_in,
                              void* d_out, int out_size) {
    const float* x = (const float*)d_in[0];   // [512, 256] f32
    const float* w = (const float*)d_in[1];   // [256, 256, 49] f32
    float* out = (float*)d_out;               // [512, 256] f32
    (void)in_sizes; (void)n_in; (void)out_size;

    // 1) direct transpose w -> wt[k][o]
    {
        dim3 grid(KDIM / 128, OUT_F / 32);    // (98, 8)
        transpose_w_kernel<<<grid, 256>>>(w);
    }
    // 2) main contraction (fused basis) into split-K partials
    {
        dim3 grid(BATCH / B_TILE, 2, I_SPLIT);  // (4, 2, 37) = 296 CTAs = 2/SM
        pp_main_kernel<<<grid, 256>>>(x);
    }
    // 3) reduce partials
    {
        reduce_kernel<<<512, 512>>>(out);
    }
}

// round 10
// speedup vs baseline: 1.1405x; 1.1405x over previous
#include <cuda_runtime.h>
#include <cuda_fp16.h>

// Problem constants (fixed shapes per reference)
#define IN_F     256
#define OUT_F    256
#define BATCH    512
#define NSEG     16
#define NT       49            // (N-1)*SEGMENTS + 1
#define KDIM     (IN_F * NT)   // 12544

// i split into 37 uneven pieces so grid = 4 * 37 = 148 = #SMs.
// Splits 0..33 have 7 i's, splits 34..36 have 6 (34*7 + 3*6 = 256).
#define I_SPLIT  37
#define I_MAX    7
#define B_TILE   128
#define B_SUB    16                 // per thread (8 b-lanes * 16 = 128)

// Static device scratch (no allocations allowed)
__device__ __half g_wt_h[KDIM * OUT_F];               // transposed weights [k][o] fp16, 6.4 MB
__device__ float  g_part[I_SPLIT * BATCH * OUT_F];    // split-K partials, 18.5 MB

// ---------------------------------------------------------------------------
// Kernel 1: DIRECT transpose + fp32->fp16 convert:  w[o][k] -> wt_h[k][o].
// Thread (lane = o, warp covers 16 k each): reads 64 B contiguous (4 x LDG.128),
// writes 16 STG.U16, each warp-coalesced (64 B lines along o).
// Grid (KDIM/128, OUT_F/32) = (98, 8), block 256.
// ---------------------------------------------------------------------------
__global__ __launch_bounds__(256) void transpose_w_kernel(const float* __restrict__ w) {
    const int t     = threadIdx.x;
    const int lane  = t & 31;                         // o within tile
    const int wrp   = t >> 5;                         // 0..7
    const int o     = blockIdx.y * 32 + lane;
    const int kbase = blockIdx.x * 128 + wrp * 16;    // 16 consecutive k per thread

    const float* src = w + (size_t)o * KDIM + kbase;
    const float4 v0 = __ldg((const float4*)(src + 0));
    const float4 v1 = __ldg((const float4*)(src + 4));
    const float4 v2 = __ldg((const float4*)(src + 8));
    const float4 v3 = __ldg((const float4*)(src + 12));

    float vv[16] = { v0.x, v0.y, v0.z, v0.w,
                     v1.x, v1.y, v1.z, v1.w,
                     v2.x, v2.y, v2.z, v2.w,
                     v3.x, v3.y, v3.z, v3.w };

    __half* dst = g_wt_h + (size_t)kbase * OUT_F + o;
#pragma unroll
    for (int c = 0; c < 16; c++) {
        dst[(size_t)c * OUT_F] = __float2half_rn(vv[c]);
    }
}

// ---------------------------------------------------------------------------
// Kernel 2 (main): fused basis + fp16-weight gather-contraction.
// Grid: (4 b-tiles, 37 i-splits) = 148 CTAs = exactly one per SM.
// Block: 512 threads = 64 o-quads x 8 b-lanes. Each thread: 16 b x 4 o x (6|7) i.
// Weights fp16 (LDG.64 per row), converted to fp32; basis + accum fp32.
// Chebyshev-Lobatto n=4 nodes: [-1, -0.5, 0.5, 1].
// ---------------------------------------------------------------------------
__global__ __launch_bounds__(512, 1) void pp_main_kernel(const float* __restrict__ x) {
    __shared__ float4 s_bas[I_MAX][B_TILE];
    __shared__ int    s_off[I_MAX][B_TILE];

    const int tid   = threadIdx.x;
    const int oq    = tid & 63;          // o = 4*oq
    const int blane = tid >> 6;          // 0..7 (uniform per warp)
    const int bt0   = blockIdx.x * B_TILE;
    const int split = blockIdx.y;        // 0..36
    const int icnt  = (split < 34) ? 7 : 6;
    const int i0    = (split < 34) ? split * 7 : 238 + (split - 34) * 6;

    // Stage basis + weight-row BYTE offsets: one thread per b-row.
    if (tid < B_TILE) {
        const int bl = tid;
        const float* xrow = x + (size_t)(bt0 + bl) * IN_F + i0;
#pragma unroll
        for (int il = 0; il < I_MAX; il++) {
            if (il >= icnt) break;
            const float xv = xrow[il];

            int s = (int)((xv + 1.0f) * 0.5f * (float)NSEG);
            s = min(max(s, 0), NSEG - 1);
            const float xmin = (float)s * (2.0f / (float)NSEG) - 1.0f;
            const float xi   = (xv - xmin) * (float)NSEG - 1.0f;

            const float d0 = xi + 1.0f;
            const float d1 = xi + 0.5f;
            const float d2 = xi - 0.5f;
            const float d3 = xi - 1.0f;

            float4 b;
            b.x = d1 * d2 * d3 * (-1.0f / 1.5f);
            b.y = d0 * d2 * d3 * ( 1.0f / 0.75f);
            b.z = d0 * d1 * d3 * (-1.0f / 0.75f);
            b.w = d0 * d1 * d2 * ( 1.0f / 1.5f);

            s_bas[il][bl] = b;
            s_off[il][bl] = 3 * s * (OUT_F * 2);   // byte offset (fp16 rows)
        }
    }
    __syncthreads();

    float4 acc[B_SUB];
#pragma unroll
    for (int bb = 0; bb < B_SUB; bb++) acc[bb] = make_float4(0.f, 0.f, 0.f, 0.f);

    const int bloc0 = blane * B_SUB;

#pragma unroll 1
    for (int ii = 0; ii < icnt; ii++) {
        const char* wt_i = (const char*)(g_wt_h + (size_t)(i0 + ii) * (NT * OUT_F) + oq * 4);

#pragma unroll
        for (int bb = 0; bb < B_SUB; bb++) {
            const float4 bas = s_bas[ii][bloc0 + bb];   // warp-uniform broadcast
            const int    off = s_off[ii][bloc0 + bb];

            const char* p = wt_i + off;                 // rows OUT_F*2 bytes apart
            const uint2 q0 = __ldg((const uint2*)(p + 0 * (OUT_F * 2)));
            const uint2 q1 = __ldg((const uint2*)(p + 1 * (OUT_F * 2)));
            const uint2 q2 = __ldg((const uint2*)(p + 2 * (OUT_F * 2)));
            const uint2 q3 = __ldg((const uint2*)(p + 3 * (OUT_F * 2)));

            const float2 a0 = __half22float2(*reinterpret_cast<const __half2*>(&q0.x));
            const float2 a1 = __half22float2(*reinterpret_cast<const __half2*>(&q0.y));
            const float2 b0 = __half22float2(*reinterpret_cast<const __half2*>(&q1.x));
            const float2 b1 = __half22float2(*reinterpret_cast<const __half2*>(&q1.y));
            const float2 c0 = __half22float2(*reinterpret_cast<const __half2*>(&q2.x));
            const float2 c1 = __half22float2(*reinterpret_cast<const __half2*>(&q2.y));
            const float2 e0 = __half22float2(*reinterpret_cast<const __half2*>(&q3.x));
            const float2 e1 = __half22float2(*reinterpret_cast<const __half2*>(&q3.y));

            acc[bb].x = fmaf(bas.x, a0.x, fmaf(bas.y, b0.x, fmaf(bas.z, c0.x, fmaf(bas.w, e0.x, acc[bb].x))));
            acc[bb].y = fmaf(bas.x, a0.y, fmaf(bas.y, b0.y, fmaf(bas.z, c0.y, fmaf(bas.w, e0.y, acc[bb].y))));
            acc[bb].z = fmaf(bas.x, a1.x, fmaf(bas.y, b1.x, fmaf(bas.z, c1.x, fmaf(bas.w, e1.x, acc[bb].z))));
            acc[bb].w = fmaf(bas.x, a1.y, fmaf(bas.y, b1.y, fmaf(bas.z, c1.y, fmaf(bas.w, e1.y, acc[bb].w))));
        }
    }

    float* outp = g_part + (size_t)split * (BATCH * OUT_F);
#pragma unroll
    for (int bb = 0; bb < B_SUB; bb++) {
        const int b = bt0 + bloc0 + bb;
        *(float4*)(outp + (size_t)b * OUT_F + oq * 4) = acc[bb];
    }
}

// ---------------------------------------------------------------------------
// Kernel 3: reduce the 37 i-split partials. Block = 512 threads =
// 64 outputs x 8 k-groups (5/5/5/5/5/4/4/4 partials each); fixed-order tree.
// Grid = 512 CTAs.
// ---------------------------------------------------------------------------
__global__ __launch_bounds__(512) void reduce_kernel(float* __restrict__ out) {
    __shared__ float4 sm[512];
    const int tid = threadIdx.x;
    const int o4  = blockIdx.x * 64 + (tid & 63);   // float4 index, 0..32767
    const int kg  = tid >> 6;                        // 0..7

    const int start = (kg < 5) ? kg * 5 : 25 + (kg - 5) * 4;
    const int cnt   = (kg < 5) ? 5 : 4;

    const float4* p = (const float4*)g_part + o4;
    float4 s = make_float4(0.f, 0.f, 0.f, 0.f);
#pragma unroll
    for (int k = 0; k < 5; k++) {
        if (k >= cnt) break;
        float4 v = __ldg(p + (size_t)(start + k) * (BATCH * OUT_F / 4));
        s.x += v.x; s.y += v.y; s.z += v.z; s.w += v.w;
    }
    sm[tid] = s;
    __syncthreads();

    if (kg < 2) {
        float4 a = sm[tid], b = sm[tid + 128], c = sm[tid + 256], d = sm[tid + 384];
        float4 r;
        r.x = ((a.x + b.x) + c.x) + d.x;
        r.y = ((a.y + b.y) + c.y) + d.y;
        r.z = ((a.z + b.z) + c.z) + d.z;
        r.w = ((a.w + b.w) + c.w) + d.w;
        sm[tid] = r;
    }
    __syncthreads();
    if (kg == 0) {
        float4 a = sm[tid], b = sm[tid + 64];
        float4 r;
        r.x = a.x + b.x; r.y = a.y + b.y; r.z = a.z + b.z; r.w = a.w + b.w;
        ((float4*)out)[o4] = r;
    }
}

// ---------------------------------------------------------------------------
extern "C" void kernel_launch(void* const* d_in, const int* in_sizes, int n_in,
                              void* d_out, int out_size) {
    const float* x = (const float*)d_in[0];   // [512, 256] f32
    const float* w = (const float*)d_in[1];   // [256, 256, 49] f32
    float* out = (float*)d_out;               // [512, 256] f32
    (void)in_sizes; (void)n_in; (void)out_size;

    // 1) direct transpose + fp16 convert: w -> wt_h[k][o]
    {
        dim3 grid(KDIM / 128, OUT_F / 32);    // (98, 8)
        transpose_w_kernel<<<grid, 256>>>(w);
    }
    // 2) main contraction (fused basis) into split-K partials
    {
        dim3 grid(BATCH / B_TILE, I_SPLIT);   // (4, 37) = 148 CTAs = #SMs
        pp_main_kernel<<<grid, 512>>>(x);
    }
    // 3) reduce partials
    {
        reduce_kernel<<<512, 512>>>(out);
    }
}